// round 3
// baseline (speedup 1.0000x reference)
#include <cuda_runtime.h>
#include <cuda_bf16.h>

#define NT 48
#define SEQ 512
#define BATCH 1024
#define BPB 2                     // batches per block
#define HALF 24                   // i-elements per thread (2-way split)
#define THREADS (BPB * NT * 2)    // 192 threads = 6 full warps

// Viterbi forward, i-dimension split 2-way per (b,j):
//   thread layout within a 96-thread batch group: r = j*2 + h  (partners adjacent lanes)
//   - T[i, j] half-column (24 values) cached in registers
//   - state vector in SMEM, double buffered, ONE barrier per step
//   - partner merge via shfl_xor(1) (same warp, no barrier)
//   - exact first-occurrence argmax tie-break everywhere (bit-exact vs jnp)
__global__ __launch_bounds__(THREADS, 4)
void crf_viterbi_kernel(const float* __restrict__ pot,
                        const float* __restrict__ trans,
                        float* __restrict__ out)
{
    __shared__ __align__(16) float st[2][BPB][NT];

    const int tid = threadIdx.x;
    const int grp = tid / (2 * NT);      // local batch 0/1
    const int r   = tid - grp * 2 * NT;
    const int j   = r >> 1;              // tag column
    const int h   = r & 1;               // which half of i-range
    const int b   = blockIdx.x * BPB + grp;
    const int ibase = h * HALF;

    // Cache this thread's half of transition column T[i][j]
    float tc[HALF];
#pragma unroll
    for (int k = 0; k < HALF; k++) tc[k] = trans[(ibase + k) * NT + j];

    const float* potb = pot + (size_t)b * SEQ * NT + j;
    float* bpp        = out + (size_t)b * (SEQ - 1) * NT + j;
    float* scores     = out + (size_t)BATCH * (SEQ - 1) * NT;

    // init_state = potentials[:, 0]
    float ns = potb[0];
    if (h == 0) st[0][grp][j] = ns;
    __syncthreads();

    // 2-deep prefetch of unary potentials, running pointer
    const float* pp = potb + 3 * NT;
    float pn1 = potb[NT];
    float pn2 = potb[2 * NT];
    int buf = 0;

    for (int t = 1; t < SEQ; ++t) {
        const float p = pn1;
        pn1 = pn2;
        if (t + 2 < SEQ) { pn2 = *pp; pp += NT; }

        // Load this thread's 24 state values via 6x LDS.128 (broadcast per (grp,h))
        float stt[HALF];
        const float4* sp = (const float4*)(&st[buf][grp][ibase]);
#pragma unroll
        for (int k = 0; k < HALF / 4; k++) {
            float4 v = sp[k];
            stt[4 * k + 0] = v.x; stt[4 * k + 1] = v.y;
            stt[4 * k + 2] = v.z; stt[4 * k + 3] = v.w;
        }

        // Two strict-> ascending chains (first-occurrence within each chain)
        float mA = stt[0]  + tc[0];  int iA = ibase;
        float mB = stt[12] + tc[12]; int iB = ibase + 12;
#pragma unroll
        for (int k = 1; k < 12; k++) {
            float sa = stt[k]      + tc[k];
            float sb = stt[12 + k] + tc[12 + k];
            if (sa > mA) { mA = sa; iA = ibase + k; }
            if (sb > mB) { mB = sb; iB = ibase + 12 + k; }
        }
        // Chain merge: B's indices are all higher -> strict > only
        float m; int idx;
        if (mB > mA) { m = mB; idx = iB; } else { m = mA; idx = iA; }

        // Partner merge across halves (adjacent lane, same warp).
        // Tie -> lower index wins (h=0's indices always lower): exact argmax.
        const float mo = __shfl_xor_sync(0xffffffffu, m, 1);
        const int   io = __shfl_xor_sync(0xffffffffu, idx, 1);
        if (mo > m || (mo == m && io < idx)) { m = mo; idx = io; }

        ns = p + m;                        // bit-exact vs reference
        if (h == 0) st[buf ^ 1][grp][j] = ns;   // publish new state
        else        bpp[0] = (float)idx;        // publish backpointer
        bpp += NT;
        __syncthreads();
        buf ^= 1;
    }

    if (h == 0) scores[(size_t)b * NT + j] = ns;
}

extern "C" void kernel_launch(void* const* d_in, const int* in_sizes, int n_in,
                              void* d_out, int out_size)
{
    const float* pot   = (const float*)d_in[0];
    const float* trans = (const float*)d_in[1];
    float* out         = (float*)d_out;
    crf_viterbi_kernel<<<BATCH / BPB, THREADS>>>(pot, trans, out);
}

// round 4
// speedup vs baseline: 1.8472x; 1.8472x over previous
#include <cuda_runtime.h>
#include <cuda_bf16.h>

#define NT 48
#define SEQ 512
#define BATCH 1024
#define BPB 2                 // batches per block
#define THREADS (BPB * NT)    // 96 threads = 3 warps

// Balanced max-tree over 24 floats (23 FMNMX, depth 5). Exact (max associative).
__device__ __forceinline__ float max24(const float* s) {
    float a[12];
#pragma unroll
    for (int k = 0; k < 12; k++) a[k] = fmaxf(s[2 * k], s[2 * k + 1]);
    float b0 = fmaxf(a[0], a[1]),  b1 = fmaxf(a[2], a[3]);
    float b2 = fmaxf(a[4], a[5]),  b3 = fmaxf(a[6], a[7]);
    float b4 = fmaxf(a[8], a[9]),  b5 = fmaxf(a[10], a[11]);
    float c0 = fmaxf(b0, b1), c1 = fmaxf(b2, b3), c2 = fmaxf(b4, b5);
    return fmaxf(fmaxf(c0, c1), c2);
}

// Balanced min-tree over 24 floats.
__device__ __forceinline__ float min24(const float* s) {
    float a[12];
#pragma unroll
    for (int k = 0; k < 12; k++) a[k] = fminf(s[2 * k], s[2 * k + 1]);
    float b0 = fminf(a[0], a[1]),  b1 = fminf(a[2], a[3]);
    float b2 = fminf(a[4], a[5]),  b3 = fminf(a[6], a[7]);
    float b4 = fminf(a[8], a[9]),  b5 = fminf(a[10], a[11]);
    float c0 = fminf(b0, b1), c1 = fminf(b2, b3), c2 = fminf(b4, b5);
    return fminf(fminf(c0, c1), c2);
}

// Viterbi forward: one thread per (batch, tag_j).
//   - T[:, j] column in 48 registers
//   - state in SMEM, double buffered, one barrier per step
//   - value max: balanced FMNMX trees (no 13-cyc predicated-guard chains)
//   - argmax: root-half select + equality scan of winning half, float indices,
//     min-tree for first-occurrence. Bit-exact vs jnp.max / jnp.argmax.
__global__ __launch_bounds__(THREADS, 4)
void crf_viterbi_kernel(const float* __restrict__ pot,
                        const float* __restrict__ trans,
                        float* __restrict__ out)
{
    __shared__ __align__(16) float st[2][BPB][NT];

    const int tid = threadIdx.x;
    const int lb  = tid / NT;
    const int j   = tid - lb * NT;
    const int b   = blockIdx.x * BPB + lb;

    // Transition column T[i][j] in registers
    float tc[NT];
#pragma unroll
    for (int i = 0; i < NT; i++) tc[i] = trans[i * NT + j];

    const float* potb = pot + (size_t)b * SEQ * NT + j;
    float* bpp        = out + (size_t)b * (SEQ - 1) * NT + j;
    float* scores     = out + (size_t)BATCH * (SEQ - 1) * NT;

    float ns = potb[0];
    st[0][lb][j] = ns;
    __syncthreads();

    // 2-deep prefetch of unary potentials, running pointer
    const float* pp = potb + 3 * NT;
    float pn1 = potb[NT];
    float pn2 = potb[2 * NT];
    int buf = 0;

#pragma unroll 2
    for (int t = 1; t < SEQ; ++t) {
        const float p = pn1;
        pn1 = pn2;
        if (t + 2 < SEQ) { pn2 = *pp; pp += NT; }

        // Load state (12x LDS.128, broadcast within batch group) and add tc
        float s[NT];
        const float4* sp = (const float4*)st[buf][lb];
#pragma unroll
        for (int k = 0; k < NT / 4; k++) {
            float4 v = sp[k];
            s[4 * k + 0] = v.x + tc[4 * k + 0];
            s[4 * k + 1] = v.y + tc[4 * k + 1];
            s[4 * k + 2] = v.z + tc[4 * k + 2];
            s[4 * k + 3] = v.w + tc[4 * k + 3];
        }

        // Value max via two balanced trees + root
        const float L = max24(s);
        const float R = max24(s + 24);
        const bool  pr = (R > L);          // strict: tie -> left half (lower idx)
        const float m  = pr ? R : L;
        const float kb = pr ? 24.0f : 0.0f;

        // Argmax: scan only the winning half for first equality with m
        float cand[24];
#pragma unroll
        for (int k = 0; k < 24; k++) {
            const float cs = pr ? s[k + 24] : s[k];   // SEL between two regs
            cand[k] = (cs == m) ? (float)k : 99.0f;   // FSETP + FSEL
        }
        const float fidx = min24(cand) + kb;          // first occurrence

        ns = p + m;                        // bit-exact vs reference
        st[buf ^ 1][lb][j] = ns;
        bpp[0] = fidx;                     // backpointer as float (layout confirmed)
        bpp += NT;
        __syncthreads();
        buf ^= 1;
    }

    scores[(size_t)b * NT + j] = ns;
}

extern "C" void kernel_launch(void* const* d_in, const int* in_sizes, int n_in,
                              void* d_out, int out_size)
{
    const float* pot   = (const float*)d_in[0];
    const float* trans = (const float*)d_in[1];
    float* out         = (float*)d_out;
    crf_viterbi_kernel<<<BATCH / BPB, THREADS>>>(pot, trans, out);
}